// round 15
// baseline (speedup 1.0000x reference)
#include <cuda_runtime.h>
#include <math.h>

#define LQ    512
#define KNN   64
#define DM    256
#define DP    128
#define DS    32
#define NL0   32
#define NRBF  36
#define MH    64
#define MOUT  38

// ---------------- scratch (static device arrays; no allocation) ----------------
__device__ float g_node_feat[LQ * NL0];
__device__ __align__(16) float g_W2pad[MH * 48];
__device__ __align__(16) float g_b2pad[48];
__device__ __align__(16) float g_We1g[DP * 32];   // g_pair[c] * W_e1[c][j]
__device__ float g_S1[32];
__device__ float g_S2[32];
__device__ float g_m0[LQ * 32];       // full m0 column sums per residue
__device__ float g_o1p[LQ * 2 * 12];  // per-half out1 sums (9 used)

__device__ __forceinline__ float wsum(float v) {
#pragma unroll
    for (int o = 16; o; o >>= 1) v += __shfl_xor_sync(0xffffffffu, v, o);
    return v;
}
__device__ __forceinline__ void wsum2(float& a, float& b) {
#pragma unroll
    for (int o = 16; o; o >>= 1) {
        a += __shfl_xor_sync(0xffffffffu, a, o);
        b += __shfl_xor_sync(0xffffffffu, b, o);
    }
}

// ---- packed f32x2 helpers (lanewise exact fp32) ----
__device__ __forceinline__ unsigned long long pack2(float a) {
    unsigned long long r;
    asm("mov.b64 %0, {%1, %1};" : "=l"(r) : "f"(a));
    return r;
}
__device__ __forceinline__ unsigned long long pack2f(float lo, float hi) {
    unsigned long long r;
    asm("mov.b64 %0, {%1, %2};" : "=l"(r) : "f"(lo), "f"(hi));
    return r;
}
__device__ __forceinline__ void ffma2(unsigned long long& d, unsigned long long a, unsigned long long b) {
    asm("fma.rn.f32x2 %0, %1, %2, %0;" : "+l"(d) : "l"(a), "l"(b));
}
__device__ __forceinline__ float2 unpack2(unsigned long long v) {
    float x, y;
    asm("mov.b64 {%0, %1}, %2;" : "=f"(x), "=f"(y) : "l"(v));
    return make_float2(x, y);
}

// ---- warp-register bitonic helpers ----
__device__ __forceinline__ unsigned long long shflx64(unsigned long long v, int m) {
    unsigned lo = __shfl_xor_sync(0xffffffffu, (unsigned)v, m);
    unsigned hi = __shfl_xor_sync(0xffffffffu, (unsigned)(v >> 32), m);
    return ((unsigned long long)hi << 32) | lo;
}
__device__ __forceinline__ void ce64(unsigned long long& r, int j, bool up, int lane) {
    unsigned long long p = shflx64(r, j);
    bool lower = ((lane & j) == 0);
    bool kmin = (lower == up);
    bool pless = (p < r);
    r = (kmin == pless) ? p : r;
}
__device__ __forceinline__ void sort64(unsigned long long& r0, unsigned long long& r1,
                                       bool dir, int lane) {
#pragma unroll
    for (int k = 2; k <= 64; k <<= 1) {
#pragma unroll 6
        for (int j = k >> 1; j > 0; j >>= 1) {
            if (j == 32) {
                unsigned long long lo = (r0 < r1) ? r0 : r1;
                unsigned long long hi = (r0 < r1) ? r1 : r0;
                r0 = dir ? lo : hi; r1 = dir ? hi : lo;
            } else {
                bool up0, up1;
                if (k == 64)      { up0 = dir;  up1 = dir;  }
                else if (k == 32) { up0 = dir;  up1 = !dir; }
                else { bool u = (((lane & k) == 0) == dir); up0 = u; up1 = u; }
                ce64(r0, j, up0, lane);
                ce64(r1, j, up1, lane);
            }
        }
    }
}
__device__ __forceinline__ void merge64(unsigned long long& r0, unsigned long long& r1,
                                        bool dir, int lane) {
    {
        unsigned long long lo = (r0 < r1) ? r0 : r1;
        unsigned long long hi = (r0 < r1) ? r1 : r0;
        r0 = dir ? lo : hi; r1 = dir ? hi : lo;
    }
#pragma unroll
    for (int j = 16; j > 0; j >>= 1) {
        ce64(r0, j, dir, lane);
        ce64(r1, j, dir, lane);
    }
}

// ---------------- Kernel A: node features (0..63) + weight prep (64) ----------------
__global__ void __launch_bounds__(256) prep_kernel(
    const float* __restrict__ msa, const float* __restrict__ seq1hot,
    const float* __restrict__ state,
    const float* __restrict__ g_msa, const float* __restrict__ b_msa,
    const float* __restrict__ g_state, const float* __restrict__ b_state,
    const float* __restrict__ W_x, const float* __restrict__ b_x,
    const float* __restrict__ g_node, const float* __restrict__ b_node,
    const float* __restrict__ W2, const float* __restrict__ b2,
    const float* __restrict__ g_pair, const float* __restrict__ b_pair,
    const float* __restrict__ W_e1, const float* __restrict__ b_e1)
{
    __shared__ __align__(16) float smem_f[2560];
    int tid = threadIdx.x;
    int w = tid >> 5, lane = tid & 31;

    if (blockIdx.x < 64) {
        int l = blockIdx.x * 8 + w;
        float* sx = smem_f + w * 312;

        float m[8]; float s0 = 0.f;
#pragma unroll
        for (int q = 0; q < 8; q++) { m[q] = msa[l * DM + lane + 32 * q]; s0 += m[q]; }
        float mu = wsum(s0) * (1.f / DM);
        float v0 = 0.f;
#pragma unroll
        for (int q = 0; q < 8; q++) { float d = m[q] - mu; v0 += d * d; }
        float rs = rsqrtf(wsum(v0) * (1.f / DM) + 1e-5f);
#pragma unroll
        for (int q = 0; q < 8; q++) {
            int c = lane + 32 * q;
            sx[c] = (m[q] - mu) * rs * g_msa[c] + b_msa[c];
        }
        if (lane < 21) sx[DM + lane] = seq1hot[l * 21 + lane];
        {
            float st = state[l * DS + lane];
            float mu2 = wsum(st) * (1.f / DS);
            float d = st - mu2;
            float rs2 = rsqrtf(wsum(d * d) * (1.f / DS) + 1e-5f);
            sx[DM + 21 + lane] = d * rs2 * g_state[lane] + b_state[lane];
        }
        __syncwarp();

        float a0 = b_x[lane], a1 = 0.f, a2 = 0.f, a3 = 0.f;
        for (int c = 0; c < 308; c += 4) {
            a0 = fmaf(sx[c + 0], __ldg(W_x + (c + 0) * NL0 + lane), a0);
            a1 = fmaf(sx[c + 1], __ldg(W_x + (c + 1) * NL0 + lane), a1);
            a2 = fmaf(sx[c + 2], __ldg(W_x + (c + 2) * NL0 + lane), a2);
            a3 = fmaf(sx[c + 3], __ldg(W_x + (c + 3) * NL0 + lane), a3);
        }
        float acc = (a0 + a1) + (a2 + a3) + sx[308] * __ldg(W_x + 308 * NL0 + lane);

        float mu3 = wsum(acc) * (1.f / NL0);
        float d3 = acc - mu3;
        float rs3 = rsqrtf(wsum(d3 * d3) * (1.f / NL0) + 1e-5f);
        g_node_feat[l * NL0 + lane] = d3 * rs3 * g_node[lane] + b_node[lane];
    } else {
        for (int i = tid; i < MH * 48; i += 256) {
            int h = i / 48, c = i - h * 48;
            g_W2pad[i] = (c < MOUT) ? W2[h * MOUT + c] : 0.f;
        }
        if (tid < 48) g_b2pad[tid] = (tid < MOUT) ? b2[tid] : 0.f;
        for (int i = tid; i < DP * 32; i += 256) {
            int c = i >> 5;
            g_We1g[i] = g_pair[c] * W_e1[i];
        }
        if (tid < 32) {
            float s1 = 0.f, s2 = 0.f;
            for (int c = 0; c < DP; c++) {
                float wv = W_e1[c * 32 + tid];
                s1 = fmaf(g_pair[c], wv, s1);
                s2 = fmaf(b_pair[c], wv, s2);
            }
            g_S1[tid] = s1;
            g_S2[tid] = s2 + b_e1[tid];
        }
    }
}

// ---------------- Kernel B: full-residue edge MLP with inline top-64 ----------------
// smem layout (floats), P=64 pairs, stride 65
#define OFF_INVT   0        // 103*65 = 6695 (prologue: aliased as topk key buffer)
#define OFF_BUF    6695     // 64*65 = 4160
#define OFF_GVGD   10855    // 64*6 = 384
#define OFF_MURS   11239    // 128
#define OFF_HBASE  11367    // 64
#define OFF_GNE1   11431    // 32
#define OFF_BNE1   11463    // 32
#define OFF_NODEI  11495    // 32
#define OFF_CA     11527    // 4
#define OFF_WV     11531    // 12
#define OFF_NBR    11543    // 64 ints
#define OFF_RELHAT 11607    // 192
#define OFF_SCA    11799    // 1536 (CA coords of all residues)
#define SMEMF      13335

__global__ void __launch_bounds__(256, 4) pair_kernel(
    const float* __restrict__ xyz, const float* __restrict__ pair,
    const float* __restrict__ g_ne1, const float* __restrict__ b_ne1,
    const float* __restrict__ W1, const float* __restrict__ b1,
    const float* __restrict__ Wv)
{
    extern __shared__ float s[];
    int l = blockIdx.x;
    int tid = threadIdx.x;
    int w = tid >> 5, lane = tid & 31;

    // ---- stage CA coords + small vectors ----
    for (int j = tid; j < LQ; j += 256) {
        s[OFF_SCA + j * 3 + 0] = xyz[j * 9 + 3];
        s[OFF_SCA + j * 3 + 1] = xyz[j * 9 + 4];
        s[OFF_SCA + j * 3 + 2] = xyz[j * 9 + 5];
    }
    if (tid < 32) {
        s[OFF_GNE1 + tid] = g_ne1[tid];
        s[OFF_BNE1 + tid] = b_ne1[tid];
        s[OFF_NODEI + tid] = g_node_feat[l * NL0 + tid];
    }
    if (tid < 3) s[OFF_CA + tid] = xyz[l * 9 + 3 + tid];
    if (tid < 9) s[OFF_WV + tid] = Wv[tid];
    __syncthreads();

    // ---- inline top-64 of 512 (register bitonic; keys alias INVT region) ----
    {
        unsigned long long* ks = (unsigned long long*)(s + OFF_INVT);  // 768 u64
        float cx = s[OFF_SCA + l * 3 + 0], cy = s[OFF_SCA + l * 3 + 1], cz = s[OFF_SCA + l * 3 + 2];
        int j0 = w * 64 + lane, j1 = j0 + 32;
        float dx0 = s[OFF_SCA + j0 * 3 + 0] - cx, dy0 = s[OFF_SCA + j0 * 3 + 1] - cy, dz0 = s[OFF_SCA + j0 * 3 + 2] - cz;
        float d20 = dx0 * dx0 + dy0 * dy0 + dz0 * dz0;
        if (j0 == l) d20 += 1e9f;
        float dx1 = s[OFF_SCA + j1 * 3 + 0] - cx, dy1 = s[OFF_SCA + j1 * 3 + 1] - cy, dz1 = s[OFF_SCA + j1 * 3 + 2] - cz;
        float d21 = dx1 * dx1 + dy1 * dy1 + dz1 * dz1;
        if (j1 == l) d21 += 1e9f;
        unsigned long long k0 = (((unsigned long long)__float_as_uint(d20)) << 32) | (unsigned)j0;
        unsigned long long k1 = (((unsigned long long)__float_as_uint(d21)) << 32) | (unsigned)j1;

        sort64(k0, k1, (w & 1) == 0, lane);
        ks[w * 64 + lane] = k0;
        ks[w * 64 + 32 + lane] = k1;
        __syncthreads();

        if (w < 4) {
            int ba = (2 * w) * 64, bb = (2 * w + 1) * 64;
            unsigned long long a0 = ks[ba + lane], a1 = ks[ba + 32 + lane];
            unsigned long long c0 = ks[bb + lane], c1 = ks[bb + 32 + lane];
            k0 = (a0 < c0) ? a0 : c0;
            k1 = (a1 < c1) ? a1 : c1;
            merge64(k0, k1, (w & 1) == 0, lane);
            ks[512 + w * 64 + lane] = k0;
            ks[512 + w * 64 + 32 + lane] = k1;
        }
        __syncthreads();

        if (w < 2) {
            int ba = 512 + (2 * w) * 64, bb = 512 + (2 * w + 1) * 64;
            unsigned long long a0 = ks[ba + lane], a1 = ks[ba + 32 + lane];
            unsigned long long c0 = ks[bb + lane], c1 = ks[bb + 32 + lane];
            k0 = (a0 < c0) ? a0 : c0;
            k1 = (a1 < c1) ? a1 : c1;
            merge64(k0, k1, (w & 1) == 0, lane);
            ks[w * 64 + lane] = k0;
            ks[w * 64 + 32 + lane] = k1;
        }
        __syncthreads();

        if (w == 0) {
            unsigned long long a0 = ks[lane],      a1 = ks[32 + lane];
            unsigned long long c0 = ks[64 + lane], c1 = ks[96 + lane];
            k0 = (a0 < c0) ? a0 : c0;
            k1 = (a1 < c1) ? a1 : c1;
            ((int*)(s + OFF_NBR))[lane]      = (int)(k0 & 0xffffffffull);
            ((int*)(s + OFF_NBR))[32 + lane] = (int)(k1 & 0xffffffffull);
        }
    }
    __syncthreads();

    // ---- neighbor + pair-row loads (batched) ----
    int jj[8];
#pragma unroll
    for (int t = 0; t < 8; t++)
        jj[t] = ((const int*)(s + OFF_NBR))[t * 8 + w];
    float A0[8], A1[8], A2[8], A3[8];
#pragma unroll
    for (int t = 0; t < 8; t++) {
        const float* prow = pair + ((size_t)l * LQ + jj[t]) * DP;
        A0[t] = __ldcs(prow + lane);
        A1[t] = __ldcs(prow + lane + 32);
        A2[t] = __ldcs(prow + lane + 64);
        A3[t] = __ldcs(prow + lane + 96);
    }

    // ---- hbase (warps 0,1) ----
    if (tid < 64) {
        float a = b1[tid];
#pragma unroll
        for (int c = 0; c < 32; c++)
            a = fmaf(s[OFF_NODEI + c], __ldg(W1 + c * 64 + tid), a);
        s[OFF_HBASE + tid] = a;
    }

    // ---- P1: stats + stage rows 0..63 of pn + geometry ----
    float ca0 = s[OFF_CA + 0], ca1 = s[OFF_CA + 1], ca2 = s[OFF_CA + 2];
#pragma unroll
    for (int t = 0; t < 8; t++) {
        int p = t * 8 + w;
        int j = jj[t];
        float a0 = A0[t], a1 = A1[t], a2 = A2[t], a3 = A3[t];
        float sum = a0 + a1 + a2 + a3;
        float ssq = a0 * a0 + a1 * a1 + a2 * a2 + a3 * a3;
        wsum2(sum, ssq);
        float mu = sum * (1.f / DP);
        float var = ssq * (1.f / DP) - mu * mu;
        float rs = rsqrtf(var + 1e-5f);
        s[OFF_BUF + lane * 65 + p] = a0;
        s[OFF_BUF + (lane + 32) * 65 + p] = a1;
        if (lane == 0) { s[OFF_MURS + 2 * p] = mu; s[OFF_MURS + 2 * p + 1] = rs; }

        s[OFF_INVT + lane * 65 + p] = g_node_feat[j * NL0 + lane];
        float cj0 = s[OFF_SCA + j * 3 + 0], cj1 = s[OFF_SCA + j * 3 + 1], cj2 = s[OFF_SCA + j * 3 + 2];
        float r0 = cj0 - ca0, r1 = cj1 - ca1, r2 = cj2 - ca2;
        float r = sqrtf(r0 * r0 + r1 * r1 + r2 * r2 + 1e-8f);
        {
            float c1 = (20.f / 35.f) * lane;
            float u = (r - c1) * 1.8f;
            s[OFF_INVT + (64 + lane) * 65 + p] = __expf(-u * u);
            if (lane < 4) {
                float c2 = (20.f / 35.f) * (lane + 32);
                float u2 = (r - c2) * 1.8f;
                s[OFF_INVT + (96 + lane) * 65 + p] = __expf(-u2 * u2);
            }
        }
        if (lane < 3) {
            float rel = (lane == 0) ? r0 : ((lane == 1) ? r1 : r2);
            s[OFF_RELHAT + p * 3 + lane] = rel / r;
            float b0 = xyz[j * 9 + lane * 3 + 0] - cj0;
            float b1v = xyz[j * 9 + lane * 3 + 1] - cj1;
            float b2v = xyz[j * 9 + lane * 3 + 2] - cj2;
            s[OFF_INVT + (100 + lane) * 65 + p] = sqrtf(b0 * b0 + b1v * b1v + b2v * b2v + 1e-8f);
        }
    }
    __syncthreads();

    // rows per lane: r0 = lane, r1 = lane + 32 (packed in f32x2 lanes)
    // ---- GEMM1-A (k=0..63) ----
    unsigned long long acc1[4];
    {
        int col0 = w * 4;
        acc1[0] = acc1[1] = acc1[2] = acc1[3] = 0ull;
#pragma unroll 2
        for (int c = 0; c < 64; c++) {
            unsigned long long ap = pack2f(s[OFF_BUF + c * 65 + lane],
                                           s[OFF_BUF + c * 65 + lane + 32]);
            float4 wv = __ldg((const float4*)(g_We1g + c * 32 + col0));
            ffma2(acc1[0], ap, pack2(wv.x)); ffma2(acc1[1], ap, pack2(wv.y));
            ffma2(acc1[2], ap, pack2(wv.z)); ffma2(acc1[3], ap, pack2(wv.w));
        }
    }
    __syncthreads();

    // ---- P2: stage rows 64..127 ----
#pragma unroll
    for (int t = 0; t < 8; t++) {
        int p = t * 8 + w;
        s[OFF_BUF + lane * 65 + p] = A2[t];
        s[OFF_BUF + (lane + 32) * 65 + p] = A3[t];
    }
    __syncthreads();

    // ---- GEMM1-B (k=64..127) + LN-fold -> E_pre rows 32..63 of INVT ----
    {
        int col0 = w * 4;
#pragma unroll 2
        for (int c = 0; c < 64; c++) {
            unsigned long long ap = pack2f(s[OFF_BUF + c * 65 + lane],
                                           s[OFF_BUF + c * 65 + lane + 32]);
            float4 wv = __ldg((const float4*)(g_We1g + (64 + c) * 32 + col0));
            ffma2(acc1[0], ap, pack2(wv.x)); ffma2(acc1[1], ap, pack2(wv.y));
            ffma2(acc1[2], ap, pack2(wv.z)); ffma2(acc1[3], ap, pack2(wv.w));
        }
        float mu0 = s[OFF_MURS + 2 * lane],        rs0 = s[OFF_MURS + 2 * lane + 1];
        float mu1 = s[OFF_MURS + 2 * (lane + 32)], rs1 = s[OFF_MURS + 2 * (lane + 32) + 1];
#pragma unroll
        for (int q = 0; q < 4; q++) {
            float2 v = unpack2(acc1[q]);
            int c0 = col0 + q;
            float s1v = __ldg(g_S1 + c0), s2v = __ldg(g_S2 + c0);
            s[OFF_INVT + (32 + c0) * 65 + lane]      = rs0 * v.x - rs0 * mu0 * s1v + s2v;
            s[OFF_INVT + (32 + c0) * 65 + lane + 32] = rs1 * v.y - rs1 * mu1 * s1v + s2v;
        }
    }
    __syncthreads();

    // ---- LN over e_pre (32) per pair ----
#pragma unroll 2
    for (int t = 0; t < 8; t++) {
        int p = t * 8 + w;
        float x = s[OFF_INVT + (32 + lane) * 65 + p];
        float sum = x, ssq = x * x;
        wsum2(sum, ssq);
        float mu = sum * (1.f / 32.f);
        float var = ssq * (1.f / 32.f) - mu * mu;
        float rs = rsqrtf(var + 1e-5f);
        s[OFF_INVT + (32 + lane) * 65 + p] = (x - mu) * rs * s[OFF_GNE1 + lane] + s[OFF_BNE1 + lane];
    }
    __syncthreads();

    // ---- GEMM2: col slice w*8 -> H into BUF ----
    {
        int col0 = w * 8;
        const float* w1base = W1 + 32 * 64 + col0;
        unsigned long long acc[8];
#pragma unroll
        for (int q = 0; q < 8; q++) acc[q] = pack2(s[OFF_HBASE + col0 + q]);
#pragma unroll 2
        for (int cc = 0; cc < 103; cc++) {
            unsigned long long ap = pack2f(s[OFF_INVT + cc * 65 + lane],
                                           s[OFF_INVT + cc * 65 + lane + 32]);
            float4 w0 = __ldg((const float4*)(w1base + cc * 64));
            float4 w1v = __ldg((const float4*)(w1base + cc * 64 + 4));
            ffma2(acc[0], ap, pack2(w0.x));  ffma2(acc[1], ap, pack2(w0.y));
            ffma2(acc[2], ap, pack2(w0.z));  ffma2(acc[3], ap, pack2(w0.w));
            ffma2(acc[4], ap, pack2(w1v.x)); ffma2(acc[5], ap, pack2(w1v.y));
            ffma2(acc[6], ap, pack2(w1v.z)); ffma2(acc[7], ap, pack2(w1v.w));
        }
#pragma unroll
        for (int q = 0; q < 8; q++) {
            float2 v = unpack2(acc[q]);
            s[OFF_BUF + (col0 + q) * 65 + lane]      = fmaxf(v.x, 0.f);
            s[OFF_BUF + (col0 + q) * 65 + lane + 32] = fmaxf(v.y, 0.f);
        }
    }
    __syncthreads();

    // ---- GEMM3: col slice w*6; m0 full sums + gv/gd ----
    {
        int col0 = w * 6;
        unsigned long long acc[6];
#pragma unroll
        for (int q = 0; q < 6; q++) acc[q] = pack2(g_b2pad[col0 + q]);
#pragma unroll 2
        for (int h = 0; h < 64; h++) {
            unsigned long long ap = pack2f(s[OFF_BUF + h * 65 + lane],
                                           s[OFF_BUF + h * 65 + lane + 32]);
            float2 w0 = __ldg((const float2*)(g_W2pad + h * 48 + col0));
            float2 w1v = __ldg((const float2*)(g_W2pad + h * 48 + col0 + 2));
            float2 w2v = __ldg((const float2*)(g_W2pad + h * 48 + col0 + 4));
            ffma2(acc[0], ap, pack2(w0.x));  ffma2(acc[1], ap, pack2(w0.y));
            ffma2(acc[2], ap, pack2(w1v.x)); ffma2(acc[3], ap, pack2(w1v.y));
            ffma2(acc[4], ap, pack2(w2v.x)); ffma2(acc[5], ap, pack2(w2v.y));
        }
#pragma unroll
        for (int q = 0; q < 6; q++) {
            int cg = col0 + q;
            float2 v = unpack2(acc[q]);
            if (cg < 32) {
                float red = wsum(v.x + v.y);
                if (lane == 0) g_m0[l * 32 + cg] = red;
            } else if (cg < 38) {
                s[OFF_GVGD + lane * 6 + (cg - 32)]        = v.x;
                s[OFF_GVGD + (lane + 32) * 6 + (cg - 32)] = v.y;
            }
        }
    }
    __syncthreads();

    // ---- out1 half-sums (warps 0,1) ----
    if (tid < 64) {
        int p = lane + w * 32;
        int j = ((const int*)(s + OFF_NBR))[p];
        float cj0 = s[OFF_SCA + j * 3 + 0], cj1 = s[OFF_SCA + j * 3 + 1], cj2 = s[OFF_SCA + j * 3 + 2];
        float v1[3][3];
#pragma unroll
        for (int c = 0; c < 3; c++) {
            v1[c][0] = xyz[j * 9 + c * 3 + 0] - cj0;
            v1[c][1] = xyz[j * 9 + c * 3 + 1] - cj1;
            v1[c][2] = xyz[j * 9 + c * 3 + 2] - cj2;
        }
        float rh[3] = { s[OFF_RELHAT + p * 3 + 0], s[OFF_RELHAT + p * 3 + 1], s[OFF_RELHAT + p * 3 + 2] };
#pragma unroll
        for (int o = 0; o < 3; o++) {
            float gvv = s[OFF_GVGD + p * 6 + o];
            float gdd = s[OFF_GVGD + p * 6 + 3 + o];
            float wv0 = s[OFF_WV + o * 3 + 0], wv1 = s[OFF_WV + o * 3 + 1], wv2 = s[OFF_WV + o * 3 + 2];
#pragma unroll
            for (int d = 0; d < 3; d++) {
                float vm = wv0 * v1[0][d] + wv1 * v1[1][d] + wv2 * v1[2][d];
                float contrib = gvv * vm + gdd * rh[d];
                float red = wsum(contrib);
                if (lane == 0) g_o1p[(l * 2 + w) * 12 + o * 3 + d] = red;
            }
        }
    }
}

// ---------------- Kernel C: epilogue ----------------
__global__ void __launch_bounds__(256) epi_kernel(
    const float* __restrict__ xyz,
    const float* __restrict__ Wself, const float* __restrict__ W_lddt,
    const float* __restrict__ b_lddt,
    const float* __restrict__ g_state, const float* __restrict__ b_state,
    float* __restrict__ out)
{
    int w = threadIdx.x >> 5, lane = threadIdx.x & 31;
    int l = blockIdx.x * 8 + w;

    float acc = g_m0[l * 32 + lane] * (1.f / KNN);
#pragma unroll
    for (int c = 0; c < 32; c++)
        acc = fmaf(g_node_feat[l * NL0 + c], __ldg(Wself + c * 32 + lane), acc);
    float mu = wsum(acc) * (1.f / 32.f);
    float d = acc - mu;
    float rs = rsqrtf(wsum(d * d) * (1.f / 32.f) + 1e-5f);
    float y = d * rs * g_state[lane] + b_state[lane];
    float tot = wsum(y * W_lddt[lane]);
    if (lane == 0)
        out[LQ * 9 + l] = 1.f / (1.f + expf(-(tot + b_lddt[0])));
    if (lane < 9) {
        int o = lane / 3, dd = lane % 3;
        float o1 = (g_o1p[(l * 2 + 0) * 12 + lane] + g_o1p[(l * 2 + 1) * 12 + lane]) * (1.f / KNN);
        float o1r1 = (g_o1p[(l * 2 + 0) * 12 + 3 + dd] + g_o1p[(l * 2 + 1) * 12 + 3 + dd]) * (1.f / KNN);
        float can = xyz[l * 9 + 3 + dd] + o1r1;
        float val = o1 + ((l == 0) ? 0.f : can);
        out[(l * 3 + o) * 3 + dd] = val;
    }
}

// ---------------- launch ----------------
extern "C" void kernel_launch(void* const* d_in, const int* in_sizes, int n_in,
                              void* d_out, int out_size)
{
    const float* xyz     = (const float*)d_in[0];
    const float* state   = (const float*)d_in[1];
    const float* msa     = (const float*)d_in[2];
    const float* pair    = (const float*)d_in[3];
    const float* seq1hot = (const float*)d_in[4];
    const float* g_msa   = (const float*)d_in[8];
    const float* b_msa   = (const float*)d_in[9];
    const float* g_pair  = (const float*)d_in[10];
    const float* b_pair  = (const float*)d_in[11];
    const float* g_state = (const float*)d_in[12];
    const float* b_state = (const float*)d_in[13];
    const float* W_x     = (const float*)d_in[14];
    const float* b_x     = (const float*)d_in[15];
    const float* g_node  = (const float*)d_in[16];
    const float* b_node  = (const float*)d_in[17];
    const float* W_e1    = (const float*)d_in[18];
    const float* b_e1    = (const float*)d_in[19];
    const float* g_ne1   = (const float*)d_in[20];
    const float* b_ne1   = (const float*)d_in[21];
    const float* W1      = (const float*)d_in[22];
    const float* b1      = (const float*)d_in[23];
    const float* W2      = (const float*)d_in[24];
    const float* b2      = (const float*)d_in[25];
    const float* Wv      = (const float*)d_in[26];
    const float* Wself   = (const float*)d_in[27];
    const float* W_lddt  = (const float*)d_in[28];
    const float* b_lddt  = (const float*)d_in[29];
    float* out = (float*)d_out;

    cudaFuncSetAttribute(pair_kernel, cudaFuncAttributeMaxDynamicSharedMemorySize,
                         SMEMF * (int)sizeof(float));

    prep_kernel<<<65, 256>>>(msa, seq1hot, state,
                             g_msa, b_msa, g_state, b_state,
                             W_x, b_x, g_node, b_node, W2, b2,
                             g_pair, b_pair, W_e1, b_e1);
    pair_kernel<<<LQ, 256, SMEMF * sizeof(float)>>>(
        xyz, pair, g_ne1, b_ne1, W1, b1, Wv);
    epi_kernel<<<LQ / 8, 256>>>(xyz, Wself, W_lddt, b_lddt, g_state, b_state, out);
}